// round 1
// baseline (speedup 1.0000x reference)
#include <cuda_runtime.h>
#include <math.h>

// Problem dims
#define T_DIM 4096
#define B_DIM 8
#define C_DIM 1024
#define F_DIM 128
#define NPROJ 6
#define N6 (NPROJ * F_DIM)          // 768
#define M_DIM (T_DIM * B_DIM)       // 32768
#define G_GRP 16                    // row groups per batch for scan
#define R_ROWS (F_DIM / G_GRP)      // 8 rows per warp

#define INV_SQRT_F 0.08838834764831845f  // 1/sqrt(128)

// Scratch (static device arrays: allocation-free per harness rules)
__device__ float d_W6[(size_t)N6 * C_DIM];                       // 3 MB packed weights
__device__ float d_b6[N6];                                       // packed biases
__device__ float d_P[(size_t)M_DIM * N6];                        // 96 MB projections
__device__ float d_opart[(size_t)M_DIM * G_GRP * F_DIM];         // 256 MB partial outputs
__device__ float d_o[(size_t)M_DIM * F_DIM];                     // 16 MB reduced o

// ---------------------------------------------------------------------------
// K0: pack the 6 projection weights/biases into contiguous buffers
// Slot order: 0=A, 1=B, 2=C, 3=D, 4=I, 5=S
// ---------------------------------------------------------------------------
__global__ void pack_weights_kernel(
    const float* __restrict__ Aw, const float* __restrict__ Bw,
    const float* __restrict__ Cw, const float* __restrict__ Dw,
    const float* __restrict__ Iw, const float* __restrict__ Sw,
    const float* __restrict__ Ab, const float* __restrict__ Bb,
    const float* __restrict__ Cb, const float* __restrict__ Db,
    const float* __restrict__ Ib, const float* __restrict__ Sb)
{
    const int per = F_DIM * C_DIM;  // 131072
    int i = blockIdx.x * blockDim.x + threadIdx.x;
    if (i < per) {
        d_W6[0 * per + i] = Aw[i];
        d_W6[1 * per + i] = Bw[i];
        d_W6[2 * per + i] = Cw[i];
        d_W6[3 * per + i] = Dw[i];
        d_W6[4 * per + i] = Iw[i];
        d_W6[5 * per + i] = Sw[i];
    }
    if (i < F_DIM) {
        d_b6[0 * F_DIM + i] = Ab[i];
        d_b6[1 * F_DIM + i] = Bb[i];
        d_b6[2 * F_DIM + i] = Cb[i];
        d_b6[3 * F_DIM + i] = Db[i];
        d_b6[4 * F_DIM + i] = Ib[i];
        d_b6[5 * F_DIM + i] = Sb[i];
    }
}

// ---------------------------------------------------------------------------
// SGEMM (NT): C[m,n] = sum_k A[m*K+k] * B[n*K+k] (+ bias[n])
// BM=BN=128, BK=8, 256 threads, 8x8 per-thread tile.
// Requires M%128==0, N%128==0, K%8==0 (holds for both call sites).
// ---------------------------------------------------------------------------
__global__ void __launch_bounds__(256)
sgemm_nt_kernel(const float* __restrict__ A, const float* __restrict__ B,
                const float* __restrict__ bias, float* __restrict__ C,
                int M, int N, int K)
{
    const int BM = 128, BN = 128, BK = 8;
    __shared__ __align__(16) float As[BK][BM];
    __shared__ __align__(16) float Bs[BK][BN];

    const int bm = blockIdx.y * BM;
    const int bn = blockIdx.x * BN;
    const int tid = threadIdx.x;

    // compute-tile mapping: 16x16 threads, each 8x8
    const int tx = tid & 15;   // n direction
    const int ty = tid >> 4;   // m direction

    // loader mapping: each thread loads one float4 of A and one of B per BK-step
    const int lrow = tid >> 1;          // 0..127
    const int lcol = (tid & 1) * 4;     // 0 or 4

    float acc[8][8];
#pragma unroll
    for (int i = 0; i < 8; i++)
#pragma unroll
        for (int j = 0; j < 8; j++) acc[i][j] = 0.0f;

    const float* Aptr = A + (size_t)(bm + lrow) * K + lcol;
    const float* Bptr = B + (size_t)(bn + lrow) * K + lcol;

    for (int k0 = 0; k0 < K; k0 += BK) {
        float4 av = *(const float4*)(Aptr + k0);
        float4 bv = *(const float4*)(Bptr + k0);
        // transpose into shared
        As[lcol + 0][lrow] = av.x;
        As[lcol + 1][lrow] = av.y;
        As[lcol + 2][lrow] = av.z;
        As[lcol + 3][lrow] = av.w;
        Bs[lcol + 0][lrow] = bv.x;
        Bs[lcol + 1][lrow] = bv.y;
        Bs[lcol + 2][lrow] = bv.z;
        Bs[lcol + 3][lrow] = bv.w;
        __syncthreads();

#pragma unroll
        for (int kk = 0; kk < BK; kk++) {
            float ra[8], rb[8];
#pragma unroll
            for (int u = 0; u < 8; u++) ra[u] = As[kk][ty * 8 + u];
#pragma unroll
            for (int u = 0; u < 8; u++) rb[u] = Bs[kk][tx * 8 + u];
#pragma unroll
            for (int i = 0; i < 8; i++)
#pragma unroll
                for (int j = 0; j < 8; j++)
                    acc[i][j] = fmaf(ra[i], rb[j], acc[i][j]);
        }
        __syncthreads();
    }

    // epilogue
#pragma unroll
    for (int i = 0; i < 8; i++) {
        float* crow = C + (size_t)(bm + ty * 8 + i) * N + bn + tx * 8;
        if (bias) {
#pragma unroll
            for (int j = 0; j < 8; j++)
                crow[j] = acc[i][j] + bias[bn + tx * 8 + j];
        } else {
#pragma unroll
            for (int j = 0; j < 8; j++)
                crow[j] = acc[i][j];
        }
    }
}

// ---------------------------------------------------------------------------
// K2: sequential scan. Grid (G_GRP, B_DIM), 32 threads (one warp) per CTA.
// Warp (g, b) owns rows [g*R_ROWS, (g+1)*R_ROWS) of batch b's state.
// Lane l owns columns {l, 32+l, 64+l, 96+l}. State fully in registers.
// Writes partial outputs opart[t][b][g][j]; final state to state_out.
// ---------------------------------------------------------------------------
__device__ __forceinline__ float warp_allsum(float x) {
#pragma unroll
    for (int o = 16; o >= 1; o >>= 1)
        x += __shfl_xor_sync(0xffffffffu, x, o);
    return x;
}

__global__ void __launch_bounds__(32)
scan_kernel(const float* __restrict__ P, const float* __restrict__ state_in,
            float* __restrict__ opart, float* __restrict__ state_out)
{
    const int g = blockIdx.x;
    const int b = blockIdx.y;
    const int l = threadIdx.x;
    const int rowbase = g * R_ROWS;

    // load initial state
    float st[R_ROWS][4];
    {
        const float* sb = state_in + ((size_t)b * F_DIM + rowbase) * F_DIM;
#pragma unroll
        for (int r = 0; r < R_ROWS; r++)
#pragma unroll
            for (int q = 0; q < 4; q++)
                st[r][q] = sb[r * F_DIM + q * 32 + l];
    }

    // current-step projection values
    float ca[4], cbv[4], cdv[4], civ[4];   // column-indexed: a, b, d, i
    float cc[R_ROWS], cs[R_ROWS];          // row-indexed: c, s
    {
        const float* pb = P + (size_t)(0 * B_DIM + b) * N6;
#pragma unroll
        for (int q = 0; q < 4; q++) {
            int j = q * 32 + l;
            ca[q]  = __ldg(pb + 0 * F_DIM + j);
            cbv[q] = __ldg(pb + 1 * F_DIM + j);
            cdv[q] = __ldg(pb + 3 * F_DIM + j);
            civ[q] = __ldg(pb + 4 * F_DIM + j);
        }
#pragma unroll
        for (int r = 0; r < R_ROWS; r++) {
            cc[r] = __ldg(pb + 2 * F_DIM + rowbase + r);
            cs[r] = __ldg(pb + 5 * F_DIM + rowbase + r);
        }
    }

#pragma unroll 1
    for (int t = 0; t < T_DIM; t++) {
        // prefetch next step's projections (clamped at the end; unused garbage-free)
        const int tn = (t + 1 < T_DIM) ? (t + 1) : t;
        const float* pn = P + (size_t)(tn * B_DIM + b) * N6;
        float na[4], nbv[4], ndv[4], niv[4], nc[R_ROWS], ns[R_ROWS];
#pragma unroll
        for (int q = 0; q < 4; q++) {
            int j = q * 32 + l;
            na[q]  = __ldg(pn + 0 * F_DIM + j);
            nbv[q] = __ldg(pn + 1 * F_DIM + j);
            ndv[q] = __ldg(pn + 3 * F_DIM + j);
            niv[q] = __ldg(pn + 4 * F_DIM + j);
        }
#pragma unroll
        for (int r = 0; r < R_ROWS; r++) {
            nc[r] = __ldg(pn + 2 * F_DIM + rowbase + r);
            ns[r] = __ldg(pn + 5 * F_DIM + rowbase + r);
        }

        // gates and scaled b
        float gq[4], bbq[4];
#pragma unroll
        for (int q = 0; q < 4; q++) {
            gq[q]  = 1.0f / (1.0f + __expf(-civ[q]));
            bbq[q] = cbv[q] * INV_SQRT_F;
        }

        // v[r] = old_state row r dot a  (reduce over columns = over lanes*4)
        float v[R_ROWS];
#pragma unroll
        for (int r = 0; r < R_ROWS; r++) {
            float p = st[r][0] * ca[0];
            p = fmaf(st[r][1], ca[1], p);
            p = fmaf(st[r][2], ca[2], p);
            p = fmaf(st[r][3], ca[3], p);
            v[r] = p;
        }
#pragma unroll
        for (int r = 0; r < R_ROWS; r++) v[r] = warp_allsum(v[r]);

        // state update: st = st*g[j] + v[i]*b[j]/sqrt(F) + c[i]*d[j]
#pragma unroll
        for (int r = 0; r < R_ROWS; r++) {
#pragma unroll
            for (int q = 0; q < 4; q++) {
                float tmp = fmaf(v[r], bbq[q], cc[r] * cdv[q]);
                st[r][q] = fmaf(st[r][q], gq[q], tmp);
            }
        }

        // partial output: po[j] = sum over owned rows of s[i]*st_new[i][j]
        float po[4] = {0.f, 0.f, 0.f, 0.f};
#pragma unroll
        for (int r = 0; r < R_ROWS; r++) {
#pragma unroll
            for (int q = 0; q < 4; q++)
                po[q] = fmaf(cs[r], st[r][q], po[q]);
        }
        float* ob = opart + ((size_t)((size_t)t * B_DIM + b) * G_GRP + g) * F_DIM;
#pragma unroll
        for (int q = 0; q < 4; q++) ob[q * 32 + l] = po[q];

        // rotate prefetched values in
#pragma unroll
        for (int q = 0; q < 4; q++) {
            ca[q] = na[q]; cbv[q] = nbv[q]; cdv[q] = ndv[q]; civ[q] = niv[q];
        }
#pragma unroll
        for (int r = 0; r < R_ROWS; r++) { cc[r] = nc[r]; cs[r] = ns[r]; }
    }

    // write final state
    float* so = state_out + ((size_t)b * F_DIM + rowbase) * F_DIM;
#pragma unroll
    for (int r = 0; r < R_ROWS; r++)
#pragma unroll
        for (int q = 0; q < 4; q++)
            so[r * F_DIM + q * 32 + l] = st[r][q];
}

// ---------------------------------------------------------------------------
// K3: reduce partial outputs over G: o[row][f] = sum_g opart[row][g][f]
// ---------------------------------------------------------------------------
__global__ void reduce_opart_kernel(const float* __restrict__ opart,
                                    float* __restrict__ o)
{
    const int F4 = F_DIM / 4;  // 32
    size_t idx = (size_t)blockIdx.x * blockDim.x + threadIdx.x;
    size_t total = (size_t)M_DIM * F4;
    if (idx >= total) return;
    size_t row = idx / F4;
    int f4 = (int)(idx % F4);
    const float4* src = (const float4*)opart + row * (size_t)(G_GRP * F4) + f4;
    float4 acc = make_float4(0.f, 0.f, 0.f, 0.f);
#pragma unroll
    for (int gg = 0; gg < G_GRP; gg++) {
        float4 xv = src[(size_t)gg * F4];
        acc.x += xv.x; acc.y += xv.y; acc.z += xv.z; acc.w += xv.w;
    }
    ((float4*)o)[idx] = acc;
}

// ---------------------------------------------------------------------------
// launch
// ---------------------------------------------------------------------------
extern "C" void kernel_launch(void* const* d_in, const int* in_sizes, int n_in,
                              void* d_out, int out_size)
{
    const float* x     = (const float*)d_in[0];
    const float* state = (const float*)d_in[1];
    const float* A_w = (const float*)d_in[2];
    const float* A_b = (const float*)d_in[3];
    const float* B_w = (const float*)d_in[4];
    const float* B_b = (const float*)d_in[5];
    const float* C_w = (const float*)d_in[6];
    const float* C_b = (const float*)d_in[7];
    const float* D_w = (const float*)d_in[8];
    const float* D_b = (const float*)d_in[9];
    const float* I_w = (const float*)d_in[10];
    const float* I_b = (const float*)d_in[11];
    const float* S_w = (const float*)d_in[12];
    const float* S_b = (const float*)d_in[13];
    const float* O_w = (const float*)d_in[14];

    float* out = (float*)d_out;

    // resolve scratch symbol addresses (host API, not an allocation)
    float *W6, *b6, *P, *opart, *o;
    cudaGetSymbolAddress((void**)&W6, d_W6);
    cudaGetSymbolAddress((void**)&b6, d_b6);
    cudaGetSymbolAddress((void**)&P, d_P);
    cudaGetSymbolAddress((void**)&opart, d_opart);
    cudaGetSymbolAddress((void**)&o, d_o);

    const size_t y_elems = (size_t)M_DIM * C_DIM;            // 33554432
    const size_t st_elems = (size_t)B_DIM * F_DIM * F_DIM;   // 131072
    float* y = out;
    float* state_out =
        ((size_t)out_size >= y_elems + st_elems) ? (out + y_elems) : o;

    // K0: pack weights
    pack_weights_kernel<<<(F_DIM * C_DIM + 255) / 256, 256>>>(
        A_w, B_w, C_w, D_w, I_w, S_w, A_b, B_b, C_b, D_b, I_b, S_b);

    // K1: projections P = x @ W6^T + b6   (M=32768, N=768, K=1024)
    {
        dim3 grid(N6 / 128, M_DIM / 128);
        sgemm_nt_kernel<<<grid, 256>>>(x, W6, b6, P, M_DIM, N6, C_DIM);
    }

    // K2: scan
    {
        dim3 grid(G_GRP, B_DIM);
        scan_kernel<<<grid, 32>>>(P, state, opart, state_out);
    }

    // K3: reduce partials
    {
        size_t total = (size_t)M_DIM * (F_DIM / 4);
        reduce_opart_kernel<<<(unsigned)((total + 255) / 256), 256>>>(opart, o);
    }

    // K4: y = o @ O_w^T   (M=32768, N=1024, K=128)
    {
        dim3 grid(C_DIM / 128, M_DIM / 128);
        sgemm_nt_kernel<<<grid, 256>>>(o, O_w, nullptr, y, M_DIM, C_DIM, F_DIM);
    }
}

// round 3
// speedup vs baseline: 1.0662x; 1.0662x over previous
#include <cuda_runtime.h>
#include <math.h>
#include <stdint.h>

// Problem dims
#define T_DIM 4096
#define B_DIM 8
#define C_DIM 1024
#define F_DIM 128
#define NPROJ 6
#define N6 (NPROJ * F_DIM)          // 768
#define M_DIM (T_DIM * B_DIM)       // 32768
#define G_GRP 32                    // row groups per batch for scan
#define R_ROWS (F_DIM / G_GRP)      // 4 rows per warp

#define INV_SQRT_F 0.08838834764831845f  // 1/sqrt(128)

// ---------------------------------------------------------------------------
// Scratch (static device arrays: allocation-free per harness rules)
// ---------------------------------------------------------------------------
__device__ float d_W6[(size_t)N6 * C_DIM];                       // 3 MB packed weights
__device__ float d_b6[N6];                                       // packed biases
__device__ float d_P[(size_t)M_DIM * N6];                        // 96 MB projections
__device__ float d_opart[(size_t)M_DIM * G_GRP * F_DIM];         // 512 MB partial outputs
__device__ float d_o[(size_t)M_DIM * F_DIM];                     // 16 MB reduced o

// ---------------------------------------------------------------------------
// K0: pack the 6 projection weights/biases (slot order A,B,C,D,I,S)
// ---------------------------------------------------------------------------
__global__ void pack_weights_kernel(
    const float* __restrict__ Aw, const float* __restrict__ Bw,
    const float* __restrict__ Cw, const float* __restrict__ Dw,
    const float* __restrict__ Iw, const float* __restrict__ Sw,
    const float* __restrict__ Ab, const float* __restrict__ Bb,
    const float* __restrict__ Cb, const float* __restrict__ Db,
    const float* __restrict__ Ib, const float* __restrict__ Sb)
{
    const int per = F_DIM * C_DIM;
    int i = blockIdx.x * blockDim.x + threadIdx.x;
    if (i < per) {
        d_W6[0 * per + i] = Aw[i];
        d_W6[1 * per + i] = Bw[i];
        d_W6[2 * per + i] = Cw[i];
        d_W6[3 * per + i] = Dw[i];
        d_W6[4 * per + i] = Iw[i];
        d_W6[5 * per + i] = Sw[i];
    }
    if (i < F_DIM) {
        d_b6[0 * F_DIM + i] = Ab[i];
        d_b6[1 * F_DIM + i] = Bb[i];
        d_b6[2 * F_DIM + i] = Cb[i];
        d_b6[3 * F_DIM + i] = Db[i];
        d_b6[4 * F_DIM + i] = Ib[i];
        d_b6[5 * F_DIM + i] = Sb[i];
    }
}

// ---------------------------------------------------------------------------
// K1/K4: 3xTF32 GEMM via mma.sync (NT): C[m,n] = sum_k A[m,k]*B[n,k] (+bias)
// BM=BN=128, BK=16. 256 threads = 8 warps (4 in M x 2 in N), warp tile 32x64.
// fp32 split hi/lo once per tile during the SMEM store; SMEM stride = 20
// floats (conflict-free for the m16n8k8 fragment access pattern).
// Requires M%128==0, N%128==0, K%16==0.
// ---------------------------------------------------------------------------
#define SM_STRIDE 20

__device__ __forceinline__ float tf32_rna(float x) {
    float r;
    asm("cvt.rna.tf32.f32 %0, %1;" : "=f"(r) : "f"(x));
    return r;
}

__device__ __forceinline__ void mma_tf32(float& d0, float& d1, float& d2, float& d3,
                                         float a0, float a1, float a2, float a3,
                                         float b0, float b1) {
    asm volatile(
        "mma.sync.aligned.m16n8k8.row.col.f32.tf32.tf32.f32 "
        "{%0,%1,%2,%3}, {%4,%5,%6,%7}, {%8,%9}, {%0,%1,%2,%3};"
        : "+f"(d0), "+f"(d1), "+f"(d2), "+f"(d3)
        : "r"(__float_as_uint(a0)), "r"(__float_as_uint(a1)),
          "r"(__float_as_uint(a2)), "r"(__float_as_uint(a3)),
          "r"(__float_as_uint(b0)), "r"(__float_as_uint(b1)));
}

__global__ void __launch_bounds__(256)
tf32_gemm_kernel(const float* __restrict__ A, const float* __restrict__ B,
                 const float* __restrict__ bias, float* __restrict__ C,
                 int M, int N, int K)
{
    __shared__ __align__(16) float Ah[128 * SM_STRIDE];
    __shared__ __align__(16) float Al[128 * SM_STRIDE];
    __shared__ __align__(16) float Bh[128 * SM_STRIDE];
    __shared__ __align__(16) float Bl[128 * SM_STRIDE];

    const int tid = threadIdx.x;
    const int wid = tid >> 5;
    const int lane = tid & 31;
    const int grp = lane >> 2;     // 0..7
    const int tig = lane & 3;      // 0..3

    const int bm = blockIdx.y * 128;
    const int bn = blockIdx.x * 128;
    const int warp_m = (wid >> 1) * 32;   // 0,32,64,96
    const int warp_n = (wid & 1) * 64;    // 0,64

    // accumulators: 2 m-tiles x 8 n-tiles x 4 regs
    float acc[2][8][4];
#pragma unroll
    for (int mt = 0; mt < 2; mt++)
#pragma unroll
        for (int nt = 0; nt < 8; nt++)
#pragma unroll
            for (int q = 0; q < 4; q++) acc[mt][nt][q] = 0.0f;

    // loader mapping: 512 float4 slots per matrix, 2 per thread
    for (int k0 = 0; k0 < K; k0 += 16) {
#pragma unroll
        for (int p = 0; p < 2; p++) {
            int idx = tid + p * 256;
            int row = idx >> 2;          // 0..127
            int c4  = (idx & 3) * 4;     // 0,4,8,12
            int so  = row * SM_STRIDE + c4;

            float4 av = *(const float4*)(A + (size_t)(bm + row) * K + k0 + c4);
            float4 ah, al;
            ah.x = tf32_rna(av.x); al.x = av.x - ah.x;
            ah.y = tf32_rna(av.y); al.y = av.y - ah.y;
            ah.z = tf32_rna(av.z); al.z = av.z - ah.z;
            ah.w = tf32_rna(av.w); al.w = av.w - ah.w;
            *(float4*)(Ah + so) = ah;
            *(float4*)(Al + so) = al;

            float4 bv = *(const float4*)(B + (size_t)(bn + row) * K + k0 + c4);
            float4 bh, bl;
            bh.x = tf32_rna(bv.x); bl.x = bv.x - bh.x;
            bh.y = tf32_rna(bv.y); bl.y = bv.y - bh.y;
            bh.z = tf32_rna(bv.z); bl.z = bv.z - bh.z;
            bh.w = tf32_rna(bv.w); bl.w = bv.w - bh.w;
            *(float4*)(Bh + so) = bh;
            *(float4*)(Bl + so) = bl;
        }
        __syncthreads();

        // 3 passes: hi*hi, hi*lo, lo*hi
#pragma unroll
        for (int pass = 0; pass < 3; pass++) {
            const float* As = (pass == 2) ? Al : Ah;
            const float* Bs = (pass == 1) ? Bl : Bh;
#pragma unroll
            for (int ks = 0; ks < 2; ks++) {
                const int kk = ks * 8;
                float afr[2][4];
#pragma unroll
                for (int mt = 0; mt < 2; mt++) {
                    int r0 = warp_m + mt * 16 + grp;
                    afr[mt][0] = As[r0 * SM_STRIDE + kk + tig];
                    afr[mt][1] = As[(r0 + 8) * SM_STRIDE + kk + tig];
                    afr[mt][2] = As[r0 * SM_STRIDE + kk + tig + 4];
                    afr[mt][3] = As[(r0 + 8) * SM_STRIDE + kk + tig + 4];
                }
                float bfr[8][2];
#pragma unroll
                for (int nt = 0; nt < 8; nt++) {
                    int n0 = warp_n + nt * 8 + grp;
                    bfr[nt][0] = Bs[n0 * SM_STRIDE + kk + tig];
                    bfr[nt][1] = Bs[n0 * SM_STRIDE + kk + tig + 4];
                }
#pragma unroll
                for (int mt = 0; mt < 2; mt++)
#pragma unroll
                    for (int nt = 0; nt < 8; nt++)
                        mma_tf32(acc[mt][nt][0], acc[mt][nt][1],
                                 acc[mt][nt][2], acc[mt][nt][3],
                                 afr[mt][0], afr[mt][1], afr[mt][2], afr[mt][3],
                                 bfr[nt][0], bfr[nt][1]);
            }
        }
        __syncthreads();
    }

    // epilogue: c0,c1 at (row, 2*tig), c2,c3 at (row+8, 2*tig)
#pragma unroll
    for (int mt = 0; mt < 2; mt++) {
        int r0 = bm + warp_m + mt * 16 + grp;
#pragma unroll
        for (int nt = 0; nt < 8; nt++) {
            int col = bn + warp_n + nt * 8 + 2 * tig;
            float b0 = 0.f, b1 = 0.f;
            if (bias != nullptr) { b0 = bias[col]; b1 = bias[col + 1]; }
            float2 v0 = make_float2(acc[mt][nt][0] + b0, acc[mt][nt][1] + b1);
            float2 v1 = make_float2(acc[mt][nt][2] + b0, acc[mt][nt][3] + b1);
            *(float2*)(C + (size_t)r0 * N + col) = v0;
            *(float2*)(C + (size_t)(r0 + 8) * N + col) = v1;
        }
    }
}

// ---------------------------------------------------------------------------
// K2: sequential scan. Grid (G_GRP, B_DIM), 32 threads per CTA.
// Warp (g,b) owns R_ROWS rows; lane owns 4 columns. State in registers.
// ---------------------------------------------------------------------------
__device__ __forceinline__ float warp_allsum(float x) {
#pragma unroll
    for (int o = 16; o >= 1; o >>= 1)
        x += __shfl_xor_sync(0xffffffffu, x, o);
    return x;
}

__global__ void __launch_bounds__(32)
scan_kernel(const float* __restrict__ P, const float* __restrict__ state_in,
            float* __restrict__ opart, float* __restrict__ state_out)
{
    const int g = blockIdx.x;
    const int b = blockIdx.y;
    const int l = threadIdx.x;
    const int rowbase = g * R_ROWS;

    float st[R_ROWS][4];
    {
        const float* sb = state_in + ((size_t)b * F_DIM + rowbase) * F_DIM;
#pragma unroll
        for (int r = 0; r < R_ROWS; r++)
#pragma unroll
            for (int q = 0; q < 4; q++)
                st[r][q] = sb[r * F_DIM + q * 32 + l];
    }

    float ca[4], cbv[4], cdv[4], civ[4];
    float cc[R_ROWS], cs[R_ROWS];
    {
        const float* pb = P + (size_t)b * N6;
#pragma unroll
        for (int q = 0; q < 4; q++) {
            int j = q * 32 + l;
            ca[q]  = __ldg(pb + 0 * F_DIM + j);
            cbv[q] = __ldg(pb + 1 * F_DIM + j);
            cdv[q] = __ldg(pb + 3 * F_DIM + j);
            civ[q] = __ldg(pb + 4 * F_DIM + j);
        }
#pragma unroll
        for (int r = 0; r < R_ROWS; r++) {
            cc[r] = __ldg(pb + 2 * F_DIM + rowbase + r);
            cs[r] = __ldg(pb + 5 * F_DIM + rowbase + r);
        }
    }

#pragma unroll 1
    for (int t = 0; t < T_DIM; t++) {
        const int tn = (t + 1 < T_DIM) ? (t + 1) : t;
        const float* pn = P + (size_t)(tn * B_DIM + b) * N6;
        float na[4], nbv[4], ndv[4], niv[4], nc[R_ROWS], ns[R_ROWS];
#pragma unroll
        for (int q = 0; q < 4; q++) {
            int j = q * 32 + l;
            na[q]  = __ldg(pn + 0 * F_DIM + j);
            nbv[q] = __ldg(pn + 1 * F_DIM + j);
            ndv[q] = __ldg(pn + 3 * F_DIM + j);
            niv[q] = __ldg(pn + 4 * F_DIM + j);
        }
#pragma unroll
        for (int r = 0; r < R_ROWS; r++) {
            nc[r] = __ldg(pn + 2 * F_DIM + rowbase + r);
            ns[r] = __ldg(pn + 5 * F_DIM + rowbase + r);
        }

        float gq[4], bbq[4];
#pragma unroll
        for (int q = 0; q < 4; q++) {
            gq[q]  = 1.0f / (1.0f + __expf(-civ[q]));
            bbq[q] = cbv[q] * INV_SQRT_F;
        }

        float v[R_ROWS];
#pragma unroll
        for (int r = 0; r < R_ROWS; r++) {
            float p = st[r][0] * ca[0];
            p = fmaf(st[r][1], ca[1], p);
            p = fmaf(st[r][2], ca[2], p);
            p = fmaf(st[r][3], ca[3], p);
            v[r] = p;
        }
#pragma unroll
        for (int r = 0; r < R_ROWS; r++) v[r] = warp_allsum(v[r]);

#pragma unroll
        for (int r = 0; r < R_ROWS; r++) {
#pragma unroll
            for (int q = 0; q < 4; q++) {
                float tmp = fmaf(v[r], bbq[q], cc[r] * cdv[q]);
                st[r][q] = fmaf(st[r][q], gq[q], tmp);
            }
        }

        float po[4] = {0.f, 0.f, 0.f, 0.f};
#pragma unroll
        for (int r = 0; r < R_ROWS; r++) {
#pragma unroll
            for (int q = 0; q < 4; q++)
                po[q] = fmaf(cs[r], st[r][q], po[q]);
        }
        float* ob = opart + ((size_t)((size_t)t * B_DIM + b) * G_GRP + g) * F_DIM;
#pragma unroll
        for (int q = 0; q < 4; q++) ob[q * 32 + l] = po[q];

#pragma unroll
        for (int q = 0; q < 4; q++) {
            ca[q] = na[q]; cbv[q] = nbv[q]; cdv[q] = ndv[q]; civ[q] = niv[q];
        }
#pragma unroll
        for (int r = 0; r < R_ROWS; r++) { cc[r] = nc[r]; cs[r] = ns[r]; }
    }

    float* so = state_out + ((size_t)b * F_DIM + rowbase) * F_DIM;
#pragma unroll
    for (int r = 0; r < R_ROWS; r++)
#pragma unroll
        for (int q = 0; q < 4; q++)
            so[r * F_DIM + q * 32 + l] = st[r][q];
}

// ---------------------------------------------------------------------------
// K3: reduce partial outputs over G
// ---------------------------------------------------------------------------
__global__ void reduce_opart_kernel(const float* __restrict__ opart,
                                    float* __restrict__ o)
{
    const int F4 = F_DIM / 4;
    size_t idx = (size_t)blockIdx.x * blockDim.x + threadIdx.x;
    size_t total = (size_t)M_DIM * F4;
    if (idx >= total) return;
    size_t row = idx / F4;
    int f4 = (int)(idx % F4);
    const float4* src = (const float4*)opart + row * (size_t)(G_GRP * F4) + f4;
    float4 acc = make_float4(0.f, 0.f, 0.f, 0.f);
#pragma unroll
    for (int gg = 0; gg < G_GRP; gg++) {
        float4 xv = src[(size_t)gg * F4];
        acc.x += xv.x; acc.y += xv.y; acc.z += xv.z; acc.w += xv.w;
    }
    ((float4*)o)[idx] = acc;
}

// ---------------------------------------------------------------------------
// launch
// ---------------------------------------------------------------------------
extern "C" void kernel_launch(void* const* d_in, const int* in_sizes, int n_in,
                              void* d_out, int out_size)
{
    const float* x     = (const float*)d_in[0];
    const float* state = (const float*)d_in[1];
    const float* A_w = (const float*)d_in[2];
    const float* A_b = (const float*)d_in[3];
    const float* B_w = (const float*)d_in[4];
    const float* B_b = (const float*)d_in[5];
    const float* C_w = (const float*)d_in[6];
    const float* C_b = (const float*)d_in[7];
    const float* D_w = (const float*)d_in[8];
    const float* D_b = (const float*)d_in[9];
    const float* I_w = (const float*)d_in[10];
    const float* I_b = (const float*)d_in[11];
    const float* S_w = (const float*)d_in[12];
    const float* S_b = (const float*)d_in[13];
    const float* O_w = (const float*)d_in[14];

    float* out = (float*)d_out;

    float *W6, *b6, *P, *opart, *o;
    cudaGetSymbolAddress((void**)&W6, d_W6);
    cudaGetSymbolAddress((void**)&b6, d_b6);
    cudaGetSymbolAddress((void**)&P, d_P);
    cudaGetSymbolAddress((void**)&opart, d_opart);
    cudaGetSymbolAddress((void**)&o, d_o);

    const size_t y_elems = (size_t)M_DIM * C_DIM;
    const size_t st_elems = (size_t)B_DIM * F_DIM * F_DIM;
    float* y = out;
    float* state_out =
        ((size_t)out_size >= y_elems + st_elems) ? (out + y_elems) : o;

    // K0: pack weights
    pack_weights_kernel<<<(F_DIM * C_DIM + 255) / 256, 256>>>(
        A_w, B_w, C_w, D_w, I_w, S_w, A_b, B_b, C_b, D_b, I_b, S_b);

    // K1: P = x @ W6^T + b6   (M=32768, N=768, K=1024) via 3xTF32 mma.sync
    {
        dim3 grid(N6 / 128, M_DIM / 128);
        tf32_gemm_kernel<<<grid, 256>>>(x, W6, b6, P, M_DIM, N6, C_DIM);
    }

    // K2: scan
    {
        dim3 grid(G_GRP, B_DIM);
        scan_kernel<<<grid, 32>>>(P, state, opart, state_out);
    }

    // K3: reduce partials
    {
        size_t total = (size_t)M_DIM * (F_DIM / 4);
        reduce_opart_kernel<<<(unsigned)((total + 255) / 256), 256>>>(opart, o);
    }

    // K4: y = o @ O_w^T   (M=32768, N=1024, K=128) via 3xTF32 mma.sync
    {
        dim3 grid(C_DIM / 128, M_DIM / 128);
        tf32_gemm_kernel<<<grid, 256>>>(o, O_w, nullptr, y, M_DIM, C_DIM, F_DIM);
    }
}